// round 6
// baseline (speedup 1.0000x reference)
#include <cuda_runtime.h>

#define THREADS 256
#define PPC 8

// shared memory offsets, in floats
#define XT    0          // xp, layout: c*36 + (c>>5)*4 + j   (j = pt*4+pp), size 9248
#define WS    9248       // weight tile, [o][kk] stride 20 (16 kk + pad), size 10240
#define ES    19488      // enc (512 rows) / later dq (256 rows): o*36 + skew*4 + j, size 18464
#define LTS   37952      // lt: (pt*8+h)*132 + t*32 + d ; later staged output, size 8448
#define WSP   46400      // spectral weights: c*24 + (c>>5) + m, size 6152
#define LATS  52552      // latent: (h*4+t)*33 + d, size 1056
#define EBS   53608      // enc_b (512)
#define DBS   54120      // dec_b (256)
#define SMEM_FLOATS 54376

typedef unsigned long long u64;

__device__ __forceinline__ u64 pk2(float lo, float hi) {
    u64 r; asm("mov.b64 %0, {%1, %2};" : "=l"(r) : "f"(lo), "f"(hi)); return r;
}
__device__ __forceinline__ void ffma2(u64 &d, u64 a, u64 b) {
    asm("fma.rn.f32x2 %0, %1, %2, %0;" : "+l"(d) : "l"(a), "l"(b));
}

__global__ void __launch_bounds__(THREADS, 1)
nsb_kernel(const float* __restrict__ x,
           const float* __restrict__ wspec,
           const float* __restrict__ latent,
           const float* __restrict__ enc_w,
           const float* __restrict__ enc_b,
           const float* __restrict__ dec_w,
           const float* __restrict__ dec_b,
           float* __restrict__ out)
{
    extern __shared__ float sm[];
    float4* sm4 = (float4*)sm;
    u64*    sm2 = (u64*)sm;

    const int tid = threadIdx.x;
    const int bi  = blockIdx.x >> 7;            // 4096 CTAs: 128 per batch image
    const int hp0 = (blockIdx.x & 127) * PPC;   // first patch (Hp index) of this CTA

    // ================= cooperative loads =================
    {
        const float4* xg4 = (const float4*)x;
        const int gb = bi * 262144 + hp0;       // float4 units: x[bi, c, hp*4..]
        #pragma unroll
        for (int r = 0; r < 8; r++) {
            int idx = r * 256 + tid;            // 2048 float4 = 256 c x 8 patches
            int c = idx >> 3, pt = idx & 7;
            float4 v = xg4[gb + c * 1024 + pt];
            sm4[(XT >> 2) + c * 9 + (c >> 5) + pt] = v;
        }
        #pragma unroll
        for (int r = 0; r < 24; r++) {          // spectral weights 256x24
            int idx = r * 256 + tid;
            int c = idx / 24, m = idx - c * 24;
            sm[WSP + c * 24 + (c >> 5) + m] = wspec[idx];
        }
        #pragma unroll
        for (int r = 0; r < 4; r++) {           // latent 8x4x32
            int idx = r * 256 + tid;
            sm[LATS + (idx >> 5) * 33 + (idx & 31)] = latent[idx];
        }
        sm[EBS + tid]       = enc_b[tid];
        sm[EBS + 256 + tid] = enc_b[256 + tid];
        sm[DBS + tid]       = dec_b[tid];
    }
    __syncthreads();

    const int ow = tid >> 2;   // 0..63: output-row group for GEMMs
    const int jq = tid & 3;    // 0..3 : 8-column group (j = jq*8 .. jq*8+7)

    // ================= GEMM1: enc = enc_w(512x256) @ xp(256x32) + enc_b =================
    {
        u64 acc[8][4];
        #pragma unroll
        for (int i = 0; i < 8; i++) {
            float b = sm[EBS + ow + 64 * i];
            u64 bb = pk2(b, b);
            acc[i][0] = bb; acc[i][1] = bb; acc[i][2] = bb; acc[i][3] = bb;
        }
        const float4* wg4 = (const float4*)enc_w;
        #pragma unroll 1
        for (int kt = 0; kt < 16; kt++) {
            // load K-tile (512 rows x 16 k) as straight float4 copies
            #pragma unroll
            for (int r = 0; r < 8; r++) {
                int idx = r * 256 + tid;
                int o = idx >> 2, kq = idx & 3;
                sm4[(WS >> 2) + o * 5 + kq] = wg4[o * 64 + kt * 4 + kq];
            }
            __syncthreads();
            #pragma unroll
            for (int mm = 0; mm < 4; mm++) {      // 4 macro-steps of 4 k each
                float4 w[8];
                #pragma unroll
                for (int i = 0; i < 8; i++)
                    w[i] = sm4[(WS >> 2) + (ow + 64 * i) * 5 + mm];
                #pragma unroll
                for (int kl = 0; kl < 4; kl++) {
                    int k = kt * 16 + mm * 4 + kl;
                    int xb = k * 18 + (k >> 5) * 2 + jq * 4;   // u64 index into xt
                    u64 x0 = sm2[xb], x1 = sm2[xb + 1], x2u = sm2[xb + 2], x3 = sm2[xb + 3];
                    #pragma unroll
                    for (int i = 0; i < 8; i++) {
                        float wv = ((const float*)&w[i])[kl];
                        u64 ww = pk2(wv, wv);
                        ffma2(acc[i][0], ww, x0); ffma2(acc[i][1], ww, x1);
                        ffma2(acc[i][2], ww, x2u); ffma2(acc[i][3], ww, x3);
                    }
                }
            }
            __syncthreads();
        }
        // epilogue: es rows o, skew (o>>6)*4 floats
        #pragma unroll
        for (int i = 0; i < 8; i++) {
            int o = ow + 64 * i;
            int eb = (ES >> 1) + o * 18 + (o >> 6) * 2 + jq * 4;
            sm2[eb]     = acc[i][0]; sm2[eb + 1] = acc[i][1];
            sm2[eb + 2] = acc[i][2]; sm2[eb + 3] = acc[i][3];
        }
    }
    __syncthreads();

    // ================= attn1 (latent encoder) + spectral mixing =================
    {
        const int pt = tid >> 5, h = (tid >> 2) & 7, tt = tid & 3;
        const int qbase = LATS + (h * 4 + tt) * 33;
        float s0 = 0.f, s1 = 0.f, s2 = 0.f, s3 = 0.f;
        #pragma unroll 8
        for (int d = 0; d < 32; d++) {
            float qd = sm[qbase + d];
            float4 k4 = sm4[(ES >> 2) + (h * 64 + 2 * d) * 9 + h + pt];
            s0 = fmaf(qd, k4.x, s0); s1 = fmaf(qd, k4.y, s1);
            s2 = fmaf(qd, k4.z, s2); s3 = fmaf(qd, k4.w, s3);
        }
        float mx = fmaxf(fmaxf(s0, s1), fmaxf(s2, s3));
        float e0 = __expf(s0 - mx), e1 = __expf(s1 - mx);
        float e2 = __expf(s2 - mx), e3 = __expf(s3 - mx);
        float rs = 1.0f / (e0 + e1 + e2 + e3);
        e0 *= rs; e1 *= rs; e2 *= rs; e3 *= rs;

        const int ltb = LTS + (pt * 8 + h) * 132 + tt * 32;
        #pragma unroll 4
        for (int d = 0; d < 32; d++) {
            float qd = sm[qbase + d];
            float4 v4 = sm4[(ES >> 2) + (h * 64 + 2 * d + 1) * 9 + h + pt];
            float val = e0 * v4.x + e1 * v4.y + e2 * v4.z + e3 * v4.w + qd;
            // spectral: sum_m sin(m*th)*w[m] + cos(m*th)*w[12+m], th = val*pi/12
            float st, ct;
            __sincosf(val * 0.26179938779914946f, &st, &ct);
            int c = h * 32 + d;
            const float* w = &sm[WSP + c * 24 + h];
            float acc = w[12];                 // m=0: sin=0, cos=1
            float smv = 0.f, cmv = 1.f;
            #pragma unroll
            for (int m = 1; m < 12; m++) {
                float sn = fmaf(smv, ct, cmv * st);
                cmv = fmaf(cmv, ct, -smv * st);
                smv = sn;
                acc = fmaf(smv, w[m], acc);
                acc = fmaf(cmv, w[12 + m], acc);
            }
            sm[ltb + d] = acc + val;
        }
    }
    __syncthreads();

    // ================= GEMM2: dq = dec_w(256x256) @ xp + dec_b (into ES region) =====
    {
        u64 acc[4][4];
        #pragma unroll
        for (int i = 0; i < 4; i++) {
            float b = sm[DBS + ow + 64 * i];
            u64 bb = pk2(b, b);
            acc[i][0] = bb; acc[i][1] = bb; acc[i][2] = bb; acc[i][3] = bb;
        }
        const float4* wg4 = (const float4*)dec_w;
        #pragma unroll 1
        for (int kt = 0; kt < 16; kt++) {
            #pragma unroll
            for (int r = 0; r < 4; r++) {
                int idx = r * 256 + tid;
                int o = idx >> 2, kq = idx & 3;
                sm4[(WS >> 2) + o * 5 + kq] = wg4[o * 64 + kt * 4 + kq];
            }
            __syncthreads();
            #pragma unroll
            for (int mm = 0; mm < 4; mm++) {
                float4 w[4];
                #pragma unroll
                for (int i = 0; i < 4; i++)
                    w[i] = sm4[(WS >> 2) + (ow + 64 * i) * 5 + mm];
                #pragma unroll
                for (int kl = 0; kl < 4; kl++) {
                    int k = kt * 16 + mm * 4 + kl;
                    int xb = k * 18 + (k >> 5) * 2 + jq * 4;
                    u64 x0 = sm2[xb], x1 = sm2[xb + 1], x2u = sm2[xb + 2], x3 = sm2[xb + 3];
                    #pragma unroll
                    for (int i = 0; i < 4; i++) {
                        float wv = ((const float*)&w[i])[kl];
                        u64 ww = pk2(wv, wv);
                        ffma2(acc[i][0], ww, x0); ffma2(acc[i][1], ww, x1);
                        ffma2(acc[i][2], ww, x2u); ffma2(acc[i][3], ww, x3);
                    }
                }
            }
            __syncthreads();
        }
        // dq epilogue: skew (o>>5)*4 floats (per-head)
        #pragma unroll
        for (int i = 0; i < 4; i++) {
            int o = ow + 64 * i;
            int eb = (ES >> 1) + o * 18 + (o >> 5) * 2 + jq * 4;
            sm2[eb]     = acc[i][0]; sm2[eb + 1] = acc[i][1];
            sm2[eb + 2] = acc[i][2]; sm2[eb + 3] = acc[i][3];
        }
    }
    __syncthreads();

    // ================= attn2 (latent decoder) + residual =================
    float outv[32];
    {
        const int pt = tid >> 5, h = (tid >> 2) & 7, pp = tid & 3;
        const int j = pt * 4 + pp;
        const int dqb = ES + h * 32 * 36 + h * 4 + j;   // dq[(h*32+d)] at +d*36
        float t0 = 0.f, t1 = 0.f, t2 = 0.f, t3 = 0.f;
        #pragma unroll
        for (int d4 = 0; d4 < 8; d4++) {
            int lb = (LTS >> 2) + (pt * 8 + h) * 33 + d4;
            float4 a0 = sm4[lb], a1 = sm4[lb + 8], a2 = sm4[lb + 16], a3 = sm4[lb + 24];
            float q0 = sm[dqb + (d4 * 4 + 0) * 36];
            float q1 = sm[dqb + (d4 * 4 + 1) * 36];
            float q2 = sm[dqb + (d4 * 4 + 2) * 36];
            float q3 = sm[dqb + (d4 * 4 + 3) * 36];
            t0 += q0 * a0.x + q1 * a0.y + q2 * a0.z + q3 * a0.w;
            t1 += q0 * a1.x + q1 * a1.y + q2 * a1.z + q3 * a1.w;
            t2 += q0 * a2.x + q1 * a2.y + q2 * a2.z + q3 * a2.w;
            t3 += q0 * a3.x + q1 * a3.y + q2 * a3.z + q3 * a3.w;
        }
        float mx = fmaxf(fmaxf(t0, t1), fmaxf(t2, t3));
        float e0 = __expf(t0 - mx), e1 = __expf(t1 - mx);
        float e2 = __expf(t2 - mx), e3 = __expf(t3 - mx);
        float rs = 1.0f / (e0 + e1 + e2 + e3);
        e0 *= rs; e1 *= rs; e2 *= rs; e3 *= rs;

        #pragma unroll
        for (int d4 = 0; d4 < 8; d4++) {
            int lb = (LTS >> 2) + (pt * 8 + h) * 33 + d4;
            float4 a0 = sm4[lb], a1 = sm4[lb + 8], a2 = sm4[lb + 16], a3 = sm4[lb + 24];
            outv[d4 * 4 + 0] = e0 * a0.x + e1 * a1.x + e2 * a2.x + e3 * a3.x;
            outv[d4 * 4 + 1] = e0 * a0.y + e1 * a1.y + e2 * a2.y + e3 * a3.y;
            outv[d4 * 4 + 2] = e0 * a0.z + e1 * a1.z + e2 * a2.z + e3 * a3.z;
            outv[d4 * 4 + 3] = e0 * a0.w + e1 * a1.w + e2 * a2.w + e3 * a3.w;
        }
        // residual add (xt skewed by head -> conflict-free)
        const int xb = XT + h * 32 * 36 + h * 4 + j;
        #pragma unroll
        for (int d = 0; d < 32; d++)
            outv[d] += sm[xb + d * 36];
    }
    __syncthreads();

    // stage outputs into the (now dead) lts region: slot t replaced by pp
    {
        const int pt = tid >> 5, h = (tid >> 2) & 7, pp = tid & 3;
        #pragma unroll
        for (int d4 = 0; d4 < 8; d4++) {
            sm4[(LTS >> 2) + (pt * 8 + h) * 33 + pp * 8 + d4] =
                make_float4(outv[d4 * 4], outv[d4 * 4 + 1], outv[d4 * 4 + 2], outv[d4 * 4 + 3]);
        }
    }
    __syncthreads();

    // coalesced write-out: each (pt, pp) run is 256 contiguous floats in gmem
    {
        float4* og4 = (float4*)out;
        #pragma unroll
        for (int r = 0; r < 8; r++) {
            int idx = r * 256 + tid;
            int run = idx >> 6, c4 = idx & 63;
            int pt2 = run >> 2, pp2 = run & 3, h2 = c4 >> 3, d4 = c4 & 7;
            float4 v = sm4[(LTS >> 2) + (pt2 * 8 + h2) * 33 + pp2 * 8 + d4];
            int hp = hp0 + pt2;
            int off4 = bi * 262144 + (pp2 * 64 + (hp >> 4)) * 1024
                     + (hp & 15) * 64 + h2 * 8 + d4;
            og4[off4] = v;
        }
    }
}

extern "C" void kernel_launch(void* const* d_in, const int* in_sizes, int n_in,
                              void* d_out, int out_size) {
    (void)in_sizes; (void)n_in; (void)out_size;
    cudaFuncSetAttribute(nsb_kernel, cudaFuncAttributeMaxDynamicSharedMemorySize,
                         SMEM_FLOATS * 4);
    nsb_kernel<<<4096, THREADS, SMEM_FLOATS * 4>>>(
        (const float*)d_in[0],   // x
        (const float*)d_in[1],   // weights (spectral)
        (const float*)d_in[2],   // latent
        (const float*)d_in[3],   // enc_w
        (const float*)d_in[4],   // enc_b
        (const float*)d_in[5],   // dec_w
        (const float*)d_in[6],   // dec_b
        (float*)d_out);
}